// round 2
// baseline (speedup 1.0000x reference)
#include <cuda_runtime.h>
#include <cstdint>

// Problem constants
static constexpr int N_ = 1024;
static constexpr int K_ = 32;
static constexpr int I_ = 10000;
static constexpr int I4_ = I_ / 4;       // 2500 float4 chunks per row
static constexpr float EPS_ = 1e-10f;

__device__ __forceinline__ float lg2_approx(float v) {
    float r;
    asm("lg2.approx.f32 %0, %1;" : "=f"(r) : "f"(v));
    return r;
}
__device__ __forceinline__ float ex2_approx(float v) {
    float r;
    asm("ex2.approx.f32 %0, %1;" : "=f"(r) : "f"(v));
    return r;
}

// out[n,k] = (sum_i x[n,i] * w_i) / (sum_i w_i)
// w_i = 2^( 0.43280850*logits[k,i] - 0.1*log2(t) ),  t = -ln(u+eps)+eps
//
// The second log (log2 t) is computed WITHOUT MUFU:
//   t is always a normal positive float (t >= eps = 1e-10 > FLT_MIN), so
//   float(bits(t)) * 2^-23 - 127 == e + z  exactly, where mantissa m = 1+z.
//   log2 t = (e + z) + D(z),  D(z) = log2(1+z) - z, z in [0,1).
//   D is a degree-5 Chebyshev-fit polynomial (max abs err ~1.5e-5 in log2,
//   -> ~1e-6 relative error in w). All coefficients are pre-scaled by -0.1
//   (the 1/temperature in log2 domain), so the Horner chain directly yields
//   the -0.1*log2(t) term of the softmax score. MUFU ops: 2/elem (was 3).
__global__ void __launch_bounds__(1024, 1)
concrete_selector_kernel(const float* __restrict__ x,
                         const float* __restrict__ u,
                         const float* __restrict__ logits,
                         float* __restrict__ out) {
    __shared__ float xs[I_];   // 40000 B: x row for this n, reused by all 32 warps

    const int n   = blockIdx.x;
    const int tid = threadIdx.x;

    // Cooperative load of x[n, :] into shared (float4)
    {
        const float4* __restrict__ xg4 =
            reinterpret_cast<const float4*>(x + (size_t)n * I_);
        float4* xs4 = reinterpret_cast<float4*>(xs);
        for (int i = tid; i < I4_; i += 1024) xs4[i] = xg4[i];
    }
    __syncthreads();

    const int warp = tid >> 5;
    const int lane = tid & 31;
    const int k    = warp;    // 32 warps == 32 k's

    const float4* __restrict__ ug4 =
        reinterpret_cast<const float4*>(u + ((size_t)n * K_ + k) * (size_t)I_);
    const float4* __restrict__ cg4 =
        reinterpret_cast<const float4*>(logits + (size_t)k * I_);
    const float4* xs4 = reinterpret_cast<const float4*>(xs);

    float accA = 0.0f;   // sum x*w
    float accB = 0.0f;   // sum w

    // -0.1 * D(z) Horner coefficients (D(z) = log2(1+z) - z on [0,1)):
    //   e1..e5 = -0.1 * {0.441434, -0.706489, 0.409875, -0.188115, 0.0432743}
    //   e0 = -0.1 * 2.74e-5 folded into the 12.7 base constant.
    auto body = [&](float uu, float lgv, float xv) {
        float L   = lg2_approx(uu + EPS_);                 // MUFU
        float t   = fmaf(L, -0.69314718f, EPS_);           // -ln(u+eps)+eps
        int   ti  = __float_as_int(t);
        float m   = __int_as_float((ti & 0x007fffff) | 0x3f800000);  // 1 LOP3
        float cvt = (float)ti;                             // I2F
        float z   = m - 1.0f;
        float q   = fmaf(z, -4.32743e-3f,  1.88115e-2f);
        q         = fmaf(z, q,            -4.09875e-2f);
        q         = fmaf(z, q,             7.06489e-2f);
        q         = fmaf(z, q,            -4.41434e-2f);
        // hb = -0.1 * (e + z) :  cvt * (-0.1 * 2^-23) + 12.7 (+e0)
        float hb  = fmaf(cvt, -1.1920929e-8f, 12.69999726f);
        float sp  = fmaf(lgv, 0.43280850f, hb);            // + (3/ln2/10)*logits
        float s2  = fmaf(z, q, sp);                        // full log2-score
        float w   = ex2_approx(s2);                        // MUFU
        accB += w;
        accA  = fmaf(xv, w, accA);
    };

    constexpr int MAIN = (I4_ / 32) * 32;   // 2496: uniform main loop
    #pragma unroll 2
    for (int j = lane; j < MAIN; j += 32) {
        float4 uu = __ldcs(&ug4[j]);   // streaming, evict-first: protect L2 for logits
        float4 cc = cg4[j];
        float4 xv = xs4[j];
        body(uu.x, cc.x, xv.x);
        body(uu.y, cc.y, xv.y);
        body(uu.z, cc.z, xv.z);
        body(uu.w, cc.w, xv.w);
    }
    // Tail: chunks 2496..2499 handled by lanes 0..3
    if (lane < I4_ - MAIN) {
        int j = MAIN + lane;
        float4 uu = __ldcs(&ug4[j]);
        float4 cc = cg4[j];
        float4 xv = xs4[j];
        body(uu.x, cc.x, xv.x);
        body(uu.y, cc.y, xv.y);
        body(uu.z, cc.z, xv.z);
        body(uu.w, cc.w, xv.w);
    }

    // Warp reduction (each warp owns its own (n,k))
    #pragma unroll
    for (int off = 16; off > 0; off >>= 1) {
        accA += __shfl_down_sync(0xffffffffu, accA, off);
        accB += __shfl_down_sync(0xffffffffu, accB, off);
    }
    if (lane == 0) {
        out[(size_t)n * K_ + k] = accA / accB;
    }
}

extern "C" void kernel_launch(void* const* d_in, const int* in_sizes, int n_in,
                              void* d_out, int out_size) {
    const float* x      = (const float*)d_in[0];   // (1024, 10000)
    const float* u      = (const float*)d_in[1];   // (1024, 32, 10000)
    const float* logits = (const float*)d_in[2];   // (32, 10000)
    float* out = (float*)d_out;                    // (1024, 32)
    (void)in_sizes; (void)n_in; (void)out_size;

    concrete_selector_kernel<<<N_, 1024>>>(x, u, logits, out);
}